// round 2
// baseline (speedup 1.0000x reference)
#include <cuda_runtime.h>
#include <math_constants.h>

// Problem constants (fixed shapes from reference setup_inputs)
#define BT_   32768      // 32*1024 rows
#define D_    256        // feature dim
#define NC_   8192       // codebook size
#define ZOUT_ELEMS ((size_t)BT_ * D_)   // 8388608
// output layout: [z_out (BT*D)] [loss (1)] [idx as float (BT)]

// Static device scratch (no runtime allocation allowed)
__device__ float g_xn [BT_ * D_];   // normalized x rows (zn)
__device__ float g_cbn[NC_ * D_];   // normalized codebook (cb / zqn source)
__device__ float g_cn2[NC_];        // |cbn_j|^2
__device__ int   g_bidx[BT_];       // final argmin indices
__device__ int2  g_cand[BT_];       // top-2 candidate indices from pass 1
__device__ float g_gap [BT_];       // top-2 value gap from pass 1
__device__ float g_part[BT_ / 8];   // per-block loss partials (4096)

// ---------------------------------------------------------------------------
// Row L2-normalize: one warp per row, 8 rows per 256-thread block.
// IEEE sqrt/div so results match the reference regardless of fast-math flags.
// ---------------------------------------------------------------------------
__device__ __forceinline__ void normalize_row(const float* __restrict__ src,
                                              float* __restrict__ dst,
                                              float* __restrict__ n2out,
                                              int row) {
    int lane = threadIdx.x & 31;
    const float* r = src + (size_t)row * D_;
    float4 a = *reinterpret_cast<const float4*>(r + lane * 8);
    float4 b = *reinterpret_cast<const float4*>(r + lane * 8 + 4);
    float s = a.x*a.x + a.y*a.y + a.z*a.z + a.w*a.w
            + b.x*b.x + b.y*b.y + b.z*b.z + b.w*b.w;
    #pragma unroll
    for (int o = 16; o; o >>= 1) s += __shfl_xor_sync(0xffffffffu, s, o);
    float n = fmaxf(__fsqrt_rn(s), 1e-12f);
    float4 wa, wb;
    wa.x = __fdiv_rn(a.x, n); wa.y = __fdiv_rn(a.y, n);
    wa.z = __fdiv_rn(a.z, n); wa.w = __fdiv_rn(a.w, n);
    wb.x = __fdiv_rn(b.x, n); wb.y = __fdiv_rn(b.y, n);
    wb.z = __fdiv_rn(b.z, n); wb.w = __fdiv_rn(b.w, n);
    float* w = dst + (size_t)row * D_;
    *reinterpret_cast<float4*>(w + lane * 8)     = wa;
    *reinterpret_cast<float4*>(w + lane * 8 + 4) = wb;
    if (n2out) {
        float q = wa.x*wa.x + wa.y*wa.y + wa.z*wa.z + wa.w*wa.w
                + wb.x*wb.x + wb.y*wb.y + wb.z*wb.z + wb.w*wb.w;
        #pragma unroll
        for (int o = 16; o; o >>= 1) q += __shfl_xor_sync(0xffffffffu, q, o);
        if (lane == 0) n2out[row] = q;
    }
}

__global__ void k_norm_x(const float* __restrict__ x) {
    int row = blockIdx.x * 8 + (threadIdx.x >> 5);
    normalize_row(x, g_xn, nullptr, row);
}

__global__ void k_norm_cb(const float* __restrict__ emb) {
    int row = blockIdx.x * 8 + (threadIdx.x >> 5);
    normalize_row(emb, g_cbn, g_cn2, row);
}

// ---------------------------------------------------------------------------
// Pass 1: fused SGEMM + streaming TOP-2 argmin.
// score_j = |cb_j|^2 - 2 * (zf . cb_j)   (row-constant |zf|^2 dropped)
// BM=128 rows/block, BN=128 codes/iter, BK=16, 8x8 per-thread tile.
// Inner product uses packed fma.rn.f32x2 (FFMA2): accumulators pair along the
// row (i) dimension so A-pairs are loaded directly as 64-bit from shared.
// ---------------------------------------------------------------------------
__global__ __launch_bounds__(256, 2) void k_argmin() {
    __shared__ float smem[8192];         // 32 KB: GEMM tiles (16KB) + reduce
    float* As = smem;                    // [16][128]
    float* Bs = smem + 2048;             // [16][128]

    const int tid = threadIdx.x;
    const int tx = tid & 15;             // code-tile column group
    const int ty = tid >> 4;             // row group
    const int row0 = blockIdx.x * 128;

    float b1v[8], b2v[8];
    int   b1i[8], b2i[8];
    #pragma unroll
    for (int i = 0; i < 8; i++) {
        b1v[i] = CUDART_INF_F; b2v[i] = CUDART_INF_F;
        b1i[i] = 0;            b2i[i] = 0;
    }

    for (int n0 = 0; n0 < NC_; n0 += 128) {
        unsigned long long accP[4][8];   // packed (row 2p, row 2p+1) x col j
        #pragma unroll
        for (int p = 0; p < 4; p++)
            #pragma unroll
            for (int j = 0; j < 8; j++) accP[p][j] = 0ULL;

        for (int k0 = 0; k0 < D_; k0 += 16) {
            #pragma unroll
            for (int s = 0; s < 2; s++) {
                int f  = tid + s * 256;          // 0..511
                int r  = f >> 2;                 // 0..127
                int kq = f & 3;                  // float4 index along k
                float4 av = *reinterpret_cast<const float4*>(
                    g_xn + (size_t)(row0 + r) * D_ + k0 + kq * 4);
                As[(kq*4+0)*128 + r] = av.x;
                As[(kq*4+1)*128 + r] = av.y;
                As[(kq*4+2)*128 + r] = av.z;
                As[(kq*4+3)*128 + r] = av.w;
                float4 bv = *reinterpret_cast<const float4*>(
                    g_cbn + (size_t)(n0 + r) * D_ + k0 + kq * 4);
                Bs[(kq*4+0)*128 + r] = bv.x;
                Bs[(kq*4+1)*128 + r] = bv.y;
                Bs[(kq*4+2)*128 + r] = bv.z;
                Bs[(kq*4+3)*128 + r] = bv.w;
            }
            __syncthreads();

            #pragma unroll
            for (int kk = 0; kk < 16; kk++) {
                // A-pairs load packed straight from shared (16B aligned)
                ulonglong2 alo = *reinterpret_cast<ulonglong2*>(As + kk*128 + ty*8);
                ulonglong2 ahi = *reinterpret_cast<ulonglong2*>(As + kk*128 + ty*8 + 4);
                unsigned long long aP[4] = {alo.x, alo.y, ahi.x, ahi.y};
                float4 blo = *reinterpret_cast<float4*>(Bs + kk*128 + tx*8);
                float4 bhi = *reinterpret_cast<float4*>(Bs + kk*128 + tx*8 + 4);
                float bsc[8] = {blo.x, blo.y, blo.z, blo.w,
                                bhi.x, bhi.y, bhi.z, bhi.w};
                unsigned long long bD[8];
                #pragma unroll
                for (int j = 0; j < 8; j++)
                    asm("mov.b64 %0, {%1, %1};" : "=l"(bD[j]) : "f"(bsc[j]));
                #pragma unroll
                for (int p = 0; p < 4; p++)
                    #pragma unroll
                    for (int j = 0; j < 8; j++)
                        asm("fma.rn.f32x2 %0, %1, %2, %0;"
                            : "+l"(accP[p][j]) : "l"(aP[p]), "l"(bD[j]));
            }
            __syncthreads();
        }

        // Epilogue: fold this 128-code chunk into the running top-2
        #pragma unroll
        for (int j = 0; j < 8; j++) {
            int col = n0 + tx * 8 + j;
            float c2 = __ldg(&g_cn2[col]);
            #pragma unroll
            for (int p = 0; p < 4; p++) {
                float lo, hi;
                asm("mov.b64 {%0, %1}, %2;" : "=f"(lo), "=f"(hi) : "l"(accP[p][j]));
                float s0 = fmaf(-2.0f, lo, c2);
                float s1 = fmaf(-2.0f, hi, c2);
                const int i0 = 2*p, i1 = 2*p + 1;
                if (s0 < b1v[i0]) { b2v[i0]=b1v[i0]; b2i[i0]=b1i[i0];
                                    b1v[i0]=s0;      b1i[i0]=col; }
                else if (s0 < b2v[i0]) { b2v[i0]=s0; b2i[i0]=col; }
                if (s1 < b1v[i1]) { b2v[i1]=b1v[i1]; b2i[i1]=b1i[i1];
                                    b1v[i1]=s1;      b1i[i1]=col; }
                else if (s1 < b2v[i1]) { b2v[i1]=s1; b2i[i1]=col; }
            }
        }
    }

    // Cross-thread top-2 merge (over the 16 tx threads per row)
    __syncthreads();
    float* sv1 = smem;                                   // 2048
    float* sv2 = smem + 2048;                            // 2048
    int*   si1 = reinterpret_cast<int*>(smem + 4096);    // 2048
    int*   si2 = reinterpret_cast<int*>(smem + 6144);    // 2048
    #pragma unroll
    for (int i = 0; i < 8; i++) {
        int r = ty * 8 + i;
        sv1[r*16 + tx] = b1v[i]; si1[r*16 + tx] = b1i[i];
        sv2[r*16 + tx] = b2v[i]; si2[r*16 + tx] = b2i[i];
    }
    __syncthreads();
    if (tid < 128) {
        float v1 = CUDART_INF_F, v2 = CUDART_INF_F;
        int   j1 = 0, j2 = 0;
        #pragma unroll
        for (int c = 0; c < 16; c++) {
            float a = sv1[tid*16 + c]; int ia = si1[tid*16 + c];
            if (a < v1 || (a == v1 && ia < j1)) { v2=v1; j2=j1; v1=a; j1=ia; }
            else if (a < v2 || (a == v2 && ia < j2)) { v2=a; j2=ia; }
            float b = sv2[tid*16 + c]; int ib = si2[tid*16 + c];
            if (b < v1 || (b == v1 && ib < j1)) { v2=v1; j2=j1; v1=b; j1=ib; }
            else if (b < v2 || (b == v2 && ib < j2)) { v2=b; j2=ib; }
        }
        int row = row0 + tid;
        g_cand[row] = make_int2(j1, j2);
        g_gap[row]  = v2 - v1;
    }
}

// ---------------------------------------------------------------------------
// Pass 2: exact fp64 re-rank of near-tie rows (gap < 1e-3; noise is ~2e-7).
// One warp per row; non-contested rows just commit the pass-1 winner.
// ---------------------------------------------------------------------------
__global__ void k_rescue() {
    int warp = threadIdx.x >> 5, lane = threadIdx.x & 31;
    int row = blockIdx.x * 8 + warp;
    int2 cd = g_cand[row];
    float gap = g_gap[row];
    if (gap > 1e-3f) {
        if (lane == 0) g_bidx[row] = cd.x;
        return;
    }
    const float* xr = g_xn  + (size_t)row  * D_;
    const float* qa = g_cbn + (size_t)cd.x * D_;
    const float* qb = g_cbn + (size_t)cd.y * D_;
    double da = 0.0, db = 0.0, na = 0.0, nb = 0.0;
    #pragma unroll
    for (int u = 0; u < 8; u++) {
        int c = lane * 8 + u;
        double xv = (double)xr[c];
        double av = (double)qa[c], bv = (double)qb[c];
        da += xv * av;  db += xv * bv;
        na += av * av;  nb += bv * bv;
    }
    #pragma unroll
    for (int o = 16; o; o >>= 1) {
        da += __shfl_xor_sync(0xffffffffu, da, o);
        db += __shfl_xor_sync(0xffffffffu, db, o);
        na += __shfl_xor_sync(0xffffffffu, na, o);
        nb += __shfl_xor_sync(0xffffffffu, nb, o);
    }
    double sa = na - 2.0 * da;
    double sb = nb - 2.0 * db;
    int pick = (sb < sa || (sb == sa && cd.y < cd.x)) ? cd.y : cd.x;
    if (lane == 0) g_bidx[row] = pick;
}

// ---------------------------------------------------------------------------
// Quantize + partial loss: one warp per row.
// z_out = x + (zqn - x)  (reference rounding order), zqn = g_cbn[idx].
// ---------------------------------------------------------------------------
__global__ void k_quant(const float* __restrict__ x, float* __restrict__ out) {
    int warp = threadIdx.x >> 5, lane = threadIdx.x & 31;
    int row = blockIdx.x * 8 + warp;
    int j = g_bidx[row];
    const float* q  = g_cbn + (size_t)j   * D_;
    const float* xr = x     + (size_t)row * D_;
    const float* zn = g_xn  + (size_t)row * D_;
    float acc = 0.0f;
    #pragma unroll
    for (int u = 0; u < 8; u++) {
        int c = lane * 8 + u;
        float qv = q[c];
        float xv = xr[c];
        out[(size_t)row * D_ + c] = xv + (qv - xv);
        float dd = qv - zn[c];
        acc = fmaf(dd, dd, acc);
    }
    #pragma unroll
    for (int o = 16; o; o >>= 1) acc += __shfl_xor_sync(0xffffffffu, acc, o);
    __shared__ float ws[8];
    if (lane == 0) ws[warp] = acc;
    __syncthreads();
    if (threadIdx.x == 0) {
        float s = 0.0f;
        #pragma unroll
        for (int w = 0; w < 8; w++) s += ws[w];
        g_part[blockIdx.x] = s;
    }
    if (lane == 0) out[ZOUT_ELEMS + 1 + row] = (float)j;
}

// Deterministic final loss reduction (double accumulation for the big sum)
__global__ void k_loss(float* __restrict__ out) {
    __shared__ double sm[256];
    double s = 0.0;
    for (int i = threadIdx.x; i < BT_ / 8; i += 256) s += (double)g_part[i];
    sm[threadIdx.x] = s;
    __syncthreads();
    for (int o = 128; o; o >>= 1) {
        if (threadIdx.x < o) sm[threadIdx.x] += sm[threadIdx.x + o];
        __syncthreads();
    }
    if (threadIdx.x == 0) {
        float m = (float)(sm[0] / (double)(BT_ * D_));
        out[ZOUT_ELEMS] = 0.25f * m + m;   // BETA*mean + mean
    }
}

// ---------------------------------------------------------------------------
extern "C" void kernel_launch(void* const* d_in, const int* in_sizes, int n_in,
                              void* d_out, int out_size) {
    const float* x   = (const float*)d_in[0];  // [32,1024,256]
    const float* emb = (const float*)d_in[1];  // [8192,256]
    float* out = (float*)d_out;

    k_norm_cb<<<NC_ / 8, 256>>>(emb);     // normalized codebook + |cb|^2
    k_norm_x <<<BT_ / 8, 256>>>(x);       // normalized inputs (zn / zf)
    k_argmin <<<BT_ / 128, 256>>>();      // fused distance GEMM + top-2
    k_rescue <<<BT_ / 8, 256>>>();        // fp64 exact re-rank of near-ties
    k_quant  <<<BT_ / 8, 256>>>(x, out);  // z_out, idx, loss partials
    k_loss   <<<1, 256>>>(out);           // deterministic loss reduce
}

// round 4
// speedup vs baseline: 2.2054x; 2.2054x over previous
#include <cuda_runtime.h>
#include <cuda_fp16.h>
#include <mma.h>
#include <math_constants.h>
#include <cstdint>

using namespace nvcuda;

// Problem constants (fixed shapes from reference setup_inputs)
#define BT_   32768      // 32*1024 rows
#define D_    256        // feature dim
#define NC_   8192       // codebook size
#define ZOUT_ELEMS ((size_t)BT_ * D_)   // 8388608
// output layout: [z_out (BT*D)] [loss (1)] [idx as float (BT)]

// Static device scratch (no runtime allocation allowed)
__device__ float  g_xn [BT_ * D_];   // normalized x rows (fp32, exact)
__device__ float  g_cbn[NC_ * D_];   // normalized codebook (fp32, exact)
__device__ __half g_xh [BT_ * D_];   // fp16 copy for tensor GEMM
__device__ __half g_cbh[NC_ * D_];   // fp16 copy for tensor GEMM
__device__ int    g_top[BT_ * 8];    // noisy top-8 candidates per row
__device__ int    g_bidx[BT_];       // final argmin indices
__device__ float  g_part[BT_ / 8];   // per-block loss partials

// ===========================================================================
// cp.async helpers (sm_80+ PTX, available at compute_103)
// ===========================================================================
__device__ __forceinline__ uint32_t smem_to_u32(const void* p) {
    uint32_t a;
    asm("{ .reg .u64 t; cvta.to.shared.u64 t, %1; cvt.u32.u64 %0, t; }"
        : "=r"(a) : "l"(p));
    return a;
}
__device__ __forceinline__ void cp16(uint32_t dst, const void* src) {
    asm volatile("cp.async.cg.shared.global [%0], [%1], 16;" :: "r"(dst), "l"(src));
}
#define CP_COMMIT() asm volatile("cp.async.commit_group;" ::: "memory")
#define CP_WAIT0()  asm volatile("cp.async.wait_group 0;" ::: "memory")

// ===========================================================================
// SMEM layout for the GEMM kernel.
// Tiles: 128 rows x 256 fp16, row stride 528 B (pad 16 B: 16B-aligned,
// odd 16B-bank phase -> conflict-free for both cp.async stores and wmma loads).
// Scores (128x128 fp32, col-major ld=132) alias onto the consumed B buffer.
// ===========================================================================
#define ROWB     528                       // bytes per tile row
#define LDH      264                       // halfs per tile row
#define TILE_B   (128 * ROWB)              // 67584 B
#define SM_A     0
#define SM_B0    TILE_B
#define SM_B1    (2 * TILE_B)
#define SMEM_DYN (3 * TILE_B)              // 202752 B

// order-preserving float->u32 map (ascending)
__device__ __forceinline__ uint32_t fmap(float f) {
    uint32_t b = __float_as_uint(f);
    return b ^ ((b & 0x80000000u) ? 0xFFFFFFFFu : 0x80000000u);
}

// ===========================================================================
// Row L2-normalize (fp32 exact + fp16 copy). One warp per row.
// ===========================================================================
__device__ __forceinline__ void normalize_row(const float* __restrict__ src,
                                              float* __restrict__ dst,
                                              __half* __restrict__ hdst,
                                              int row) {
    int lane = threadIdx.x & 31;
    const float* r = src + (size_t)row * D_;
    float4 a = *reinterpret_cast<const float4*>(r + lane * 8);
    float4 b = *reinterpret_cast<const float4*>(r + lane * 8 + 4);
    float s = a.x*a.x + a.y*a.y + a.z*a.z + a.w*a.w
            + b.x*b.x + b.y*b.y + b.z*b.z + b.w*b.w;
    #pragma unroll
    for (int o = 16; o; o >>= 1) s += __shfl_xor_sync(0xffffffffu, s, o);
    float n = fmaxf(__fsqrt_rn(s), 1e-12f);
    float4 wa, wb;
    wa.x = __fdiv_rn(a.x, n); wa.y = __fdiv_rn(a.y, n);
    wa.z = __fdiv_rn(a.z, n); wa.w = __fdiv_rn(a.w, n);
    wb.x = __fdiv_rn(b.x, n); wb.y = __fdiv_rn(b.y, n);
    wb.z = __fdiv_rn(b.z, n); wb.w = __fdiv_rn(b.w, n);
    float* w = dst + (size_t)row * D_;
    *reinterpret_cast<float4*>(w + lane * 8)     = wa;
    *reinterpret_cast<float4*>(w + lane * 8 + 4) = wb;
    __half2* h = reinterpret_cast<__half2*>(hdst + (size_t)row * D_ + lane * 8);
    h[0] = __floats2half2_rn(wa.x, wa.y);
    h[1] = __floats2half2_rn(wa.z, wa.w);
    h[2] = __floats2half2_rn(wb.x, wb.y);
    h[3] = __floats2half2_rn(wb.z, wb.w);
}

__global__ void k_norm_x(const float* __restrict__ x) {
    int row = blockIdx.x * 8 + (threadIdx.x >> 5);
    normalize_row(x, g_xn, g_xh, row);
}
__global__ void k_norm_cb(const float* __restrict__ emb) {
    int row = blockIdx.x * 8 + (threadIdx.x >> 5);
    normalize_row(emb, g_cbn, g_cbh, row);
}

// ===========================================================================
// Pass 1: wmma fp16 GEMM (dot = zfn . cbn) + streaming per-row top-8.
// Block = 128 rows; 64 chunks of 128 codes; 8 warps in 4(m) x 2(n) grid,
// warp tile 32x64 via m16n16k16 fragments (B col_major = natural layout).
// Scores stored col-major into the dead B buffer; thread r owns row r's
// top-8 (packed u64 keys) across all 8192 candidates -> no reductions.
// ===========================================================================
__global__ void __launch_bounds__(256, 1) k_argmin_tc() {
    extern __shared__ char smem[];
    const uint32_t sb = smem_to_u32(smem);
    const int tid = threadIdx.x;
    const int wid = tid >> 5;
    const int wm = wid & 3;            // warp row block (32 rows)
    const int wn = wid >> 2;           // warp col block (64 cols)
    const int row0 = blockIdx.x * 128;

    // Load A tile (128 rows x 512 B) + first B chunk
    {
        const char* Ag = reinterpret_cast<const char*>(g_xh) + (size_t)row0 * 512;
        const char* Bg = reinterpret_cast<const char*>(g_cbh);
        #pragma unroll
        for (int i = 0; i < 16; i++) {
            int f = tid + i * 256;
            int r = f >> 5, c = f & 31;
            cp16(sb + SM_A + r * ROWB + c * 16, Ag + (size_t)r * 512 + c * 16);
        }
        #pragma unroll
        for (int i = 0; i < 16; i++) {
            int f = tid + i * 256;
            int r = f >> 5, c = f & 31;
            cp16(sb + SM_B0 + r * ROWB + c * 16, Bg + (size_t)r * 512 + c * 16);
        }
        CP_COMMIT();
        CP_WAIT0();
    }
    __syncthreads();

    // per-thread top-8 keys for row `tid` (only tid < 128 meaningful)
    unsigned long long top[8];
    #pragma unroll
    for (int k = 0; k < 8; k++) top[k] = 0xFFFFFFFFFFFFFFFFull;

    const __half* As = reinterpret_cast<const __half*>(smem + SM_A);

    for (int ch = 0; ch < 64; ch++) {
        const int  cur  = (ch & 1) ? SM_B1 : SM_B0;
        const int  nxt  = (ch & 1) ? SM_B0 : SM_B1;
        const __half* Bs = reinterpret_cast<const __half*>(smem + cur);

        // Prefetch next B chunk (overlaps MMA + epilogue)
        if (ch + 1 < 64) {
            const char* Bg = reinterpret_cast<const char*>(g_cbh)
                           + (size_t)(ch + 1) * 128 * 512;
            #pragma unroll
            for (int i = 0; i < 16; i++) {
                int f = tid + i * 256;
                int r = f >> 5, c = f & 31;
                cp16(sb + nxt + r * ROWB + c * 16, Bg + (size_t)r * 512 + c * 16);
            }
            CP_COMMIT();
        }

        // MMA: warp tile 32x64 = 2x4 fragments, K = 256 in 16 steps
        wmma::fragment<wmma::accumulator, 16, 16, 16, float> acc[2][4];
        #pragma unroll
        for (int i = 0; i < 2; i++)
            #pragma unroll
            for (int j = 0; j < 4; j++) wmma::fill_fragment(acc[i][j], 0.0f);

        #pragma unroll
        for (int k0 = 0; k0 < D_; k0 += 16) {
            wmma::fragment<wmma::matrix_a, 16, 16, 16, __half, wmma::row_major> af[2];
            wmma::fragment<wmma::matrix_b, 16, 16, 16, __half, wmma::col_major> bf[4];
            #pragma unroll
            for (int i = 0; i < 2; i++)
                wmma::load_matrix_sync(af[i], As + (wm*32 + i*16) * LDH + k0, LDH);
            #pragma unroll
            for (int j = 0; j < 4; j++)
                wmma::load_matrix_sync(bf[j], Bs + (wn*64 + j*16) * LDH + k0, LDH);
            #pragma unroll
            for (int i = 0; i < 2; i++)
                #pragma unroll
                for (int j = 0; j < 4; j++)
                    wmma::mma_sync(acc[i][j], af[i], bf[j], acc[i][j]);
        }
        __syncthreads();   // all warps done reading cur B -> safe to overwrite

        // Store scores col-major (ld=132) into the dead B buffer
        float* sc = reinterpret_cast<float*>(smem + cur);
        #pragma unroll
        for (int i = 0; i < 2; i++)
            #pragma unroll
            for (int j = 0; j < 4; j++)
                wmma::store_matrix_sync(sc + (wn*64 + j*16) * 132 + (wm*32 + i*16),
                                        acc[i][j], 132, wmma::mem_col_major);
        __syncthreads();

        // Scan: thread r folds its row's 128 scores into the running top-8.
        if (tid < 128) {
            const int colbase = ch * 128;
            #pragma unroll 4
            for (int c = 0; c < 128; c++) {
                float dot = sc[c * 132 + tid];
                // smaller key == larger dot; ties -> smaller col
                unsigned long long key =
                    ((unsigned long long)(~fmap(dot)) << 32) |
                    (unsigned)(colbase + c);
                if (key < top[7]) {
                    #pragma unroll
                    for (int k = 0; k < 8; k++) {
                        if (key < top[k]) {
                            unsigned long long t = top[k];
                            top[k] = key; key = t;
                        }
                    }
                }
            }
        }
        CP_WAIT0();        // next B landed (no-op on last chunk)
        __syncthreads();
    }

    if (tid < 128) {
        #pragma unroll
        for (int k = 0; k < 8; k++)
            g_top[(size_t)(row0 + tid) * 8 + k] = (int)(top[k] & 0xFFFFFFFFu);
    }
}

// ===========================================================================
// Pass 2: exact fp64 re-rank of the 8 candidates, every row. One warp/row.
// score_exact = |cbn_j|^2 - 2 * (zfn . cbn_j)   (fp32-rounded normalized vals)
// ===========================================================================
__global__ void k_rerank() {
    int warp = threadIdx.x >> 5, lane = threadIdx.x & 31;
    int row = blockIdx.x * 8 + warp;
    const float* xr = g_xn + (size_t)row * D_;
    double best = CUDART_INF;
    int bidx = 0x7fffffff;
    #pragma unroll
    for (int k = 0; k < 8; k++) {
        int j = g_top[(size_t)row * 8 + k];
        const float* q = g_cbn + (size_t)j * D_;
        double d = 0.0, n = 0.0;
        #pragma unroll
        for (int u = 0; u < 8; u++) {
            int c = lane * 8 + u;
            double qv = (double)q[c];
            d += (double)xr[c] * qv;
            n += qv * qv;
        }
        #pragma unroll
        for (int o = 16; o; o >>= 1) {
            d += __shfl_xor_sync(0xffffffffu, d, o);
            n += __shfl_xor_sync(0xffffffffu, n, o);
        }
        double s = n - 2.0 * d;
        if (s < best || (s == best && j < bidx)) { best = s; bidx = j; }
    }
    if (lane == 0) g_bidx[row] = bidx;
}

// ===========================================================================
// Quantize + partial loss: one warp per row.
// z_out = x + (zqn - x)  (reference rounding order), zqn = g_cbn[idx].
// ===========================================================================
__global__ void k_quant(const float* __restrict__ x, float* __restrict__ out) {
    int warp = threadIdx.x >> 5, lane = threadIdx.x & 31;
    int row = blockIdx.x * 8 + warp;
    int j = g_bidx[row];
    const float* q  = g_cbn + (size_t)j   * D_;
    const float* xr = x     + (size_t)row * D_;
    const float* zn = g_xn  + (size_t)row * D_;
    float acc = 0.0f;
    #pragma unroll
    for (int u = 0; u < 8; u++) {
        int c = lane * 8 + u;
        float qv = q[c];
        float xv = xr[c];
        out[(size_t)row * D_ + c] = xv + (qv - xv);
        float dd = qv - zn[c];
        acc = fmaf(dd, dd, acc);
    }
    #pragma unroll
    for (int o = 16; o; o >>= 1) acc += __shfl_xor_sync(0xffffffffu, acc, o);
    __shared__ float ws[8];
    if (lane == 0) ws[warp] = acc;
    __syncthreads();
    if (threadIdx.x == 0) {
        float s = 0.0f;
        #pragma unroll
        for (int w = 0; w < 8; w++) s += ws[w];
        g_part[blockIdx.x] = s;
    }
    if (lane == 0) out[ZOUT_ELEMS + 1 + row] = (float)j;
}

// Deterministic final loss reduction (double accumulation for the big sum)
__global__ void k_loss(float* __restrict__ out) {
    __shared__ double sm[256];
    double s = 0.0;
    for (int i = threadIdx.x; i < BT_ / 8; i += 256) s += (double)g_part[i];
    sm[threadIdx.x] = s;
    __syncthreads();
    for (int o = 128; o; o >>= 1) {
        if (threadIdx.x < o) sm[threadIdx.x] += sm[threadIdx.x + o];
        __syncthreads();
    }
    if (threadIdx.x == 0) {
        float m = (float)(sm[0] / (double)(BT_ * D_));
        out[ZOUT_ELEMS] = 0.25f * m + m;   // BETA*mean + mean
    }
}

// ===========================================================================
extern "C" void kernel_launch(void* const* d_in, const int* in_sizes, int n_in,
                              void* d_out, int out_size) {
    const float* x   = (const float*)d_in[0];  // [32,1024,256]
    const float* emb = (const float*)d_in[1];  // [8192,256]
    float* out = (float*)d_out;

    cudaFuncSetAttribute(k_argmin_tc,
                         cudaFuncAttributeMaxDynamicSharedMemorySize, SMEM_DYN);

    k_norm_cb<<<NC_ / 8, 256>>>(emb);            // normalized codebook + fp16
    k_norm_x <<<BT_ / 8, 256>>>(x);              // normalized inputs + fp16
    k_argmin_tc<<<BT_ / 128, 256, SMEM_DYN>>>(); // HMMA GEMM + top-8
    k_rerank <<<BT_ / 8, 256>>>();               // fp64 exact re-rank
    k_quant  <<<BT_ / 8, 256>>>(x, out);         // z_out, idx, loss partials
    k_loss   <<<1, 256>>>(out);                  // deterministic loss reduce
}

// round 5
// speedup vs baseline: 3.7555x; 1.7028x over previous
#include <cuda_runtime.h>
#include <cuda_fp16.h>
#include <mma.h>
#include <math_constants.h>
#include <cstdint>

using namespace nvcuda;

// Problem constants (fixed shapes from reference setup_inputs)
#define BT_   32768      // 32*1024 rows
#define D_    256        // feature dim
#define NC_   8192       // codebook size
#define ZOUT_ELEMS ((size_t)BT_ * D_)   // 8388608
// output layout: [z_out (BT*D)] [loss (1)] [idx as float (BT)]

// Static device scratch (no runtime allocation allowed)
__device__ float  g_xn [BT_ * D_];   // normalized x rows (fp32, exact)
__device__ float  g_cbn[NC_ * D_];   // normalized codebook (fp32, exact)
__device__ __half g_xh [BT_ * D_];   // fp16 copy for tensor GEMM
__device__ __half g_cbh[NC_ * D_];   // fp16 copy for tensor GEMM
__device__ int    g_top[BT_ * 8];    // noisy top-8 candidates per row
__device__ int    g_bidx[BT_];       // final argmin indices
__device__ float  g_part[BT_ / 8];   // per-block loss partials

// ===========================================================================
// cp.async helpers (sm_80+ PTX, available at compute_103)
// ===========================================================================
__device__ __forceinline__ uint32_t smem_to_u32(const void* p) {
    uint32_t a;
    asm("{ .reg .u64 t; cvta.to.shared.u64 t, %1; cvt.u32.u64 %0, t; }"
        : "=r"(a) : "l"(p));
    return a;
}
__device__ __forceinline__ void cp16(uint32_t dst, const void* src) {
    asm volatile("cp.async.cg.shared.global [%0], [%1], 16;" :: "r"(dst), "l"(src));
}
#define CP_COMMIT() asm volatile("cp.async.commit_group;" ::: "memory")
#define CP_WAIT0()  asm volatile("cp.async.wait_group 0;" ::: "memory")

// ===========================================================================
// SMEM layout for the GEMM kernel.
// Tiles: 128 rows x 256 fp16, row stride 528 B (pad 16 B: 16B-aligned,
// odd 16B-bank phase -> conflict-free for both cp.async stores and wmma loads).
// Scores (128x128 fp32, col-major ld=132) alias onto the consumed B buffer.
// ===========================================================================
#define ROWB     528                       // bytes per tile row
#define LDH      264                       // halfs per tile row
#define TILE_B   (128 * ROWB)              // 67584 B
#define SM_A     0
#define SM_B0    TILE_B
#define SM_B1    (2 * TILE_B)
#define SMEM_DYN (3 * TILE_B)              // 202752 B

// order-preserving float->u32 map (ascending)
__device__ __forceinline__ uint32_t fmap(float f) {
    uint32_t b = __float_as_uint(f);
    return b ^ ((b & 0x80000000u) ? 0xFFFFFFFFu : 0x80000000u);
}

// ===========================================================================
// Row L2-normalize (fp32 exact + fp16 copy). One warp per row.
// ===========================================================================
__device__ __forceinline__ void normalize_row(const float* __restrict__ src,
                                              float* __restrict__ dst,
                                              __half* __restrict__ hdst,
                                              int row) {
    int lane = threadIdx.x & 31;
    const float* r = src + (size_t)row * D_;
    float4 a = *reinterpret_cast<const float4*>(r + lane * 8);
    float4 b = *reinterpret_cast<const float4*>(r + lane * 8 + 4);
    float s = a.x*a.x + a.y*a.y + a.z*a.z + a.w*a.w
            + b.x*b.x + b.y*b.y + b.z*b.z + b.w*b.w;
    #pragma unroll
    for (int o = 16; o; o >>= 1) s += __shfl_xor_sync(0xffffffffu, s, o);
    float n = fmaxf(__fsqrt_rn(s), 1e-12f);
    float4 wa, wb;
    wa.x = __fdiv_rn(a.x, n); wa.y = __fdiv_rn(a.y, n);
    wa.z = __fdiv_rn(a.z, n); wa.w = __fdiv_rn(a.w, n);
    wb.x = __fdiv_rn(b.x, n); wb.y = __fdiv_rn(b.y, n);
    wb.z = __fdiv_rn(b.z, n); wb.w = __fdiv_rn(b.w, n);
    float* w = dst + (size_t)row * D_;
    *reinterpret_cast<float4*>(w + lane * 8)     = wa;
    *reinterpret_cast<float4*>(w + lane * 8 + 4) = wb;
    __half2* h = reinterpret_cast<__half2*>(hdst + (size_t)row * D_ + lane * 8);
    h[0] = __floats2half2_rn(wa.x, wa.y);
    h[1] = __floats2half2_rn(wa.z, wa.w);
    h[2] = __floats2half2_rn(wb.x, wb.y);
    h[3] = __floats2half2_rn(wb.z, wb.w);
}

__global__ void k_norm_x(const float* __restrict__ x) {
    int row = blockIdx.x * 8 + (threadIdx.x >> 5);
    normalize_row(x, g_xn, g_xh, row);
}
__global__ void k_norm_cb(const float* __restrict__ emb) {
    int row = blockIdx.x * 8 + (threadIdx.x >> 5);
    normalize_row(emb, g_cbn, g_cbh, row);
}

// ===========================================================================
// Pass 1: wmma fp16 GEMM (dot = zfn . cbn) + streaming per-row top-8.
// Block = 128 rows; 64 chunks of 128 codes; 8 warps in 4(m) x 2(n) grid.
// Epilogue: all 256 threads scan — thread t handles row (t&127), column
// half (t>>7); per-thread sorted top-8 of its half, merged once at the end
// (any global top-8 element is in its half's top-8).
// ===========================================================================
__global__ void __launch_bounds__(256, 1) k_argmin_tc() {
    extern __shared__ char smem[];
    const uint32_t sb = smem_to_u32(smem);
    const int tid = threadIdx.x;
    const int wid = tid >> 5;
    const int wm = wid & 3;            // warp row block (32 rows)
    const int wn = wid >> 2;           // warp col block (64 cols)
    const int row0 = blockIdx.x * 128;
    const int myrow = tid & 127;       // scan row
    const int chalf = (tid >> 7) * 64; // scan column-half base

    // Load A tile (128 rows x 512 B) + first B chunk
    {
        const char* Ag = reinterpret_cast<const char*>(g_xh) + (size_t)row0 * 512;
        const char* Bg = reinterpret_cast<const char*>(g_cbh);
        #pragma unroll
        for (int i = 0; i < 16; i++) {
            int f = tid + i * 256;
            int r = f >> 5, c = f & 31;
            cp16(sb + SM_A + r * ROWB + c * 16, Ag + (size_t)r * 512 + c * 16);
        }
        #pragma unroll
        for (int i = 0; i < 16; i++) {
            int f = tid + i * 256;
            int r = f >> 5, c = f & 31;
            cp16(sb + SM_B0 + r * ROWB + c * 16, Bg + (size_t)r * 512 + c * 16);
        }
        CP_COMMIT();
        CP_WAIT0();
    }
    __syncthreads();

    // per-thread sorted (ascending) top-8 keys for (myrow, chalf)
    unsigned long long top[8];
    #pragma unroll
    for (int k = 0; k < 8; k++) top[k] = 0xFFFFFFFFFFFFFFFFull;

    const __half* As = reinterpret_cast<const __half*>(smem + SM_A);

    for (int ch = 0; ch < 64; ch++) {
        const int  cur  = (ch & 1) ? SM_B1 : SM_B0;
        const int  nxt  = (ch & 1) ? SM_B0 : SM_B1;
        const __half* Bs = reinterpret_cast<const __half*>(smem + cur);

        // Prefetch next B chunk (overlaps MMA + epilogue)
        if (ch + 1 < 64) {
            const char* Bg = reinterpret_cast<const char*>(g_cbh)
                           + (size_t)(ch + 1) * 128 * 512;
            #pragma unroll
            for (int i = 0; i < 16; i++) {
                int f = tid + i * 256;
                int r = f >> 5, c = f & 31;
                cp16(sb + nxt + r * ROWB + c * 16, Bg + (size_t)r * 512 + c * 16);
            }
            CP_COMMIT();
        }

        // MMA: warp tile 32x64 = 2x4 fragments, K = 256 in 16 steps
        wmma::fragment<wmma::accumulator, 16, 16, 16, float> acc[2][4];
        #pragma unroll
        for (int i = 0; i < 2; i++)
            #pragma unroll
            for (int j = 0; j < 4; j++) wmma::fill_fragment(acc[i][j], 0.0f);

        #pragma unroll
        for (int k0 = 0; k0 < D_; k0 += 16) {
            wmma::fragment<wmma::matrix_a, 16, 16, 16, __half, wmma::row_major> af[2];
            wmma::fragment<wmma::matrix_b, 16, 16, 16, __half, wmma::col_major> bf[4];
            #pragma unroll
            for (int i = 0; i < 2; i++)
                wmma::load_matrix_sync(af[i], As + (wm*32 + i*16) * LDH + k0, LDH);
            #pragma unroll
            for (int j = 0; j < 4; j++)
                wmma::load_matrix_sync(bf[j], Bs + (wn*64 + j*16) * LDH + k0, LDH);
            #pragma unroll
            for (int i = 0; i < 2; i++)
                #pragma unroll
                for (int j = 0; j < 4; j++)
                    wmma::mma_sync(acc[i][j], af[i], bf[j], acc[i][j]);
        }
        __syncthreads();   // all warps done reading cur B -> safe to overwrite

        // Store scores col-major (ld=132) into the dead B buffer
        float* sc = reinterpret_cast<float*>(smem + cur);
        #pragma unroll
        for (int i = 0; i < 2; i++)
            #pragma unroll
            for (int j = 0; j < 4; j++)
                wmma::store_matrix_sync(sc + (wn*64 + j*16) * 132 + (wm*32 + i*16),
                                        acc[i][j], 132, wmma::mem_col_major);
        __syncthreads();

        // Scan: thread folds its 64 columns into the running sorted top-8.
        {
            const int colbase = ch * 128 + chalf;
            const float* scp = sc + chalf * 132 + myrow;
            #pragma unroll 4
            for (int c = 0; c < 64; c++) {
                float dot = scp[c * 132];
                // smaller key == larger dot; ties -> smaller col
                unsigned long long key =
                    ((unsigned long long)(~fmap(dot)) << 32) |
                    (unsigned)(colbase + c);
                if (key < top[7]) {
                    #pragma unroll
                    for (int k = 0; k < 8; k++) {
                        if (key < top[k]) {
                            unsigned long long t = top[k];
                            top[k] = key; key = t;
                        }
                    }
                }
            }
        }
        CP_WAIT0();        // next B landed (no-op on last chunk)
        __syncthreads();
    }

    // Merge the two half-lists per row (both sorted ascending)
    unsigned long long* ms = reinterpret_cast<unsigned long long*>(smem);
    #pragma unroll
    for (int k = 0; k < 8; k++) ms[tid * 8 + k] = top[k];
    __syncthreads();
    if (tid < 128) {
        const unsigned long long* la = ms + tid * 8;
        const unsigned long long* lb = ms + (tid + 128) * 8;
        int ia = 0, ib = 0;
        #pragma unroll
        for (int k = 0; k < 8; k++) {
            unsigned long long va = la[ia], vb = lb[ib];
            unsigned long long v = (va < vb) ? va : vb;
            if (va < vb) ia++; else ib++;
            g_top[(size_t)(row0 + tid) * 8 + k] = (int)(v & 0xFFFFFFFFu);
        }
    }
}

// ===========================================================================
// Pass 2: re-rank the 8 candidates. Parallel lane layout: cand = lane&7,
// seg = lane>>3 (4 segments x 64 dims). fp32 pass first; rows whose top-2
// gap < 2e-4 (noise is <2e-6) redo in fp64 with the same layout.
// score = |cbn_j|^2 - 2 * (zfn . cbn_j)
// ===========================================================================
__global__ void k_rerank() {
    const int warp = threadIdx.x >> 5, lane = threadIdx.x & 31;
    const int row = blockIdx.x * 8 + warp;
    const int cand = lane & 7;
    const int seg  = lane >> 3;          // 0..3

    const int j = g_top[(size_t)row * 8 + cand];
    const float4* x4 = reinterpret_cast<const float4*>(g_xn  + (size_t)row * D_) + seg * 16;
    const float4* q4 = reinterpret_cast<const float4*>(g_cbn + (size_t)j   * D_) + seg * 16;

    float d = 0.0f, n = 0.0f;
    #pragma unroll
    for (int u = 0; u < 16; u++) {
        float4 qa = q4[u], xa = x4[u];
        d = fmaf(xa.x, qa.x, d); d = fmaf(xa.y, qa.y, d);
        d = fmaf(xa.z, qa.z, d); d = fmaf(xa.w, qa.w, d);
        n = fmaf(qa.x, qa.x, n); n = fmaf(qa.y, qa.y, n);
        n = fmaf(qa.z, qa.z, n); n = fmaf(qa.w, qa.w, n);
    }
    // sum the 4 segments (lanes with equal lane&7)
    #pragma unroll
    for (int o = 8; o <= 16; o <<= 1) {
        d += __shfl_xor_sync(0xffffffffu, d, o);
        n += __shfl_xor_sync(0xffffffffu, n, o);
    }
    float s = n - 2.0f * d;

    // top-2 merge across the 8 candidates (lanes 0-7 pattern, replicated)
    float v1 = s, v2 = CUDART_INF_F;
    int   i1 = j, i2 = 0x7fffffff;
    #pragma unroll
    for (int o = 1; o <= 4; o <<= 1) {
        float ov1 = __shfl_xor_sync(0xffffffffu, v1, o);
        int   oi1 = __shfl_xor_sync(0xffffffffu, i1, o);
        float ov2 = __shfl_xor_sync(0xffffffffu, v2, o);
        int   oi2 = __shfl_xor_sync(0xffffffffu, i2, o);
        // merge (v1,i1,v2,i2) with (ov1,oi1,ov2,oi2)
        if (ov1 < v1 || (ov1 == v1 && oi1 < i1)) {
            v2 = v1; i2 = i1; v1 = ov1; i1 = oi1;
            if (ov2 < v2 || (ov2 == v2 && oi2 < i2)) { v2 = ov2; i2 = oi2; }
        } else {
            if (ov1 < v2 || (ov1 == v2 && oi1 < i2)) { v2 = ov1; i2 = oi1; }
        }
    }

    if (v2 - v1 >= 2e-4f) {
        if (lane == 0) g_bidx[row] = i1;
        return;
    }

    // Rare near-tie: exact fp64 redo, same layout
    const double* xd = nullptr;  // (loads below use float->double converts)
    double dd = 0.0, nn = 0.0;
    const float* xf = g_xn  + (size_t)row * D_ + seg * 64;
    const float* qf = g_cbn + (size_t)j   * D_ + seg * 64;
    #pragma unroll
    for (int u = 0; u < 64; u++) {
        double qv = (double)qf[u];
        dd += (double)xf[u] * qv;
        nn += qv * qv;
    }
    #pragma unroll
    for (int o = 8; o <= 16; o <<= 1) {
        dd += __shfl_xor_sync(0xffffffffu, dd, o);
        nn += __shfl_xor_sync(0xffffffffu, nn, o);
    }
    double sd = nn - 2.0 * dd;
    double bv = sd; int bidx = j;
    #pragma unroll
    for (int o = 1; o <= 4; o <<= 1) {
        double ov = __shfl_xor_sync(0xffffffffu, bv, o);
        int    oi = __shfl_xor_sync(0xffffffffu, bidx, o);
        if (ov < bv || (ov == bv && oi < bidx)) { bv = ov; bidx = oi; }
    }
    if (lane == 0) g_bidx[row] = bidx;
    (void)xd;
}

// ===========================================================================
// Quantize + partial loss: one warp per row.
// z_out = x + (zqn - x)  (reference rounding order), zqn = g_cbn[idx].
// ===========================================================================
__global__ void k_quant(const float* __restrict__ x, float* __restrict__ out) {
    int warp = threadIdx.x >> 5, lane = threadIdx.x & 31;
    int row = blockIdx.x * 8 + warp;
    int j = g_bidx[row];
    const float* q  = g_cbn + (size_t)j   * D_;
    const float* xr = x     + (size_t)row * D_;
    const float* zn = g_xn  + (size_t)row * D_;
    float acc = 0.0f;
    #pragma unroll
    for (int u = 0; u < 8; u++) {
        int c = lane * 8 + u;
        float qv = q[c];
        float xv = xr[c];
        out[(size_t)row * D_ + c] = xv + (qv - xv);
        float dd = qv - zn[c];
        acc = fmaf(dd, dd, acc);
    }
    #pragma unroll
    for (int o = 16; o; o >>= 1) acc += __shfl_xor_sync(0xffffffffu, acc, o);
    __shared__ float ws[8];
    if (lane == 0) ws[warp] = acc;
    __syncthreads();
    if (threadIdx.x == 0) {
        float s = 0.0f;
        #pragma unroll
        for (int w = 0; w < 8; w++) s += ws[w];
        g_part[blockIdx.x] = s;
    }
    if (lane == 0) out[ZOUT_ELEMS + 1 + row] = (float)j;
}

// Deterministic final loss reduction (double accumulation for the big sum)
__global__ void k_loss(float* __restrict__ out) {
    __shared__ double sm[256];
    double s = 0.0;
    for (int i = threadIdx.x; i < BT_ / 8; i += 256) s += (double)g_part[i];
    sm[threadIdx.x] = s;
    __syncthreads();
    for (int o = 128; o; o >>= 1) {
        if (threadIdx.x < o) sm[threadIdx.x] += sm[threadIdx.x + o];
        __syncthreads();
    }
    if (threadIdx.x == 0) {
        float m = (float)(sm[0] / (double)(BT_ * D_));
        out[ZOUT_ELEMS] = 0.25f * m + m;   // BETA*mean + mean
    }
}

// ===========================================================================
extern "C" void kernel_launch(void* const* d_in, const int* in_sizes, int n_in,
                              void* d_out, int out_size) {
    const float* x   = (const float*)d_in[0];  // [32,1024,256]
    const float* emb = (const float*)d_in[1];  // [8192,256]
    float* out = (float*)d_out;

    cudaFuncSetAttribute(k_argmin_tc,
                         cudaFuncAttributeMaxDynamicSharedMemorySize, SMEM_DYN);

    k_norm_cb<<<NC_ / 8, 256>>>(emb);            // normalized codebook + fp16
    k_norm_x <<<BT_ / 8, 256>>>(x);              // normalized inputs + fp16
    k_argmin_tc<<<BT_ / 128, 256, SMEM_DYN>>>(); // HMMA GEMM + top-8
    k_rerank <<<BT_ / 8, 256>>>();               // parallel re-rank + fp64 rescue
    k_quant  <<<BT_ / 8, 256>>>(x, out);         // z_out, idx, loss partials
    k_loss   <<<1, 256>>>(out);                  // deterministic loss reduce
}

// round 6
// speedup vs baseline: 5.1090x; 1.3604x over previous
#include <cuda_runtime.h>
#include <cuda_fp16.h>
#include <math_constants.h>
#include <cstdint>

// Problem constants (fixed shapes from reference setup_inputs)
#define BT_   32768      // 32*1024 rows
#define D_    256        // feature dim
#define NC_   8192       // codebook size
#define ZOUT_ELEMS ((size_t)BT_ * D_)   // 8388608
// output layout: [z_out (BT*D)] [loss (1)] [idx as float (BT)]

// Static device scratch (no runtime allocation allowed)
__device__ float  g_xn [BT_ * D_];   // normalized x rows (fp32, exact)
__device__ float  g_cbn[NC_ * D_];   // normalized codebook (fp32, exact)
__device__ __half g_xh [BT_ * D_];   // fp16 copy for tensor GEMM
__device__ __half g_cbh[NC_ * D_];   // fp16 copy for tensor GEMM
__device__ int    g_top[BT_ * 8];    // noisy top-8 candidates per row
__device__ int    g_bidx[BT_];       // final argmin indices
__device__ float  g_part[BT_ / 8];   // per-block loss partials

// ===========================================================================
// PTX helpers (all plain sm_80-class features; valid at compute_103)
// ===========================================================================
__device__ __forceinline__ uint32_t smem_to_u32(const void* p) {
    uint32_t a;
    asm("{ .reg .u64 t; cvta.to.shared.u64 t, %1; cvt.u32.u64 %0, t; }"
        : "=r"(a) : "l"(p));
    return a;
}
__device__ __forceinline__ void cp16(uint32_t dst, const void* src) {
    asm volatile("cp.async.cg.shared.global [%0], [%1], 16;" :: "r"(dst), "l"(src));
}
#define CP_COMMIT() asm volatile("cp.async.commit_group;" ::: "memory")
#define CP_WAIT0()  asm volatile("cp.async.wait_group 0;" ::: "memory")

__device__ __forceinline__ void ldsm_x4(uint32_t& r0, uint32_t& r1,
                                        uint32_t& r2, uint32_t& r3, uint32_t addr) {
    asm volatile("ldmatrix.sync.aligned.m8n8.x4.shared.b16 {%0,%1,%2,%3}, [%4];"
                 : "=r"(r0), "=r"(r1), "=r"(r2), "=r"(r3) : "r"(addr));
}
__device__ __forceinline__ void mma16816(float c[4],
                                         uint32_t a0, uint32_t a1, uint32_t a2, uint32_t a3,
                                         uint32_t b0, uint32_t b1) {
    asm volatile("mma.sync.aligned.m16n8k16.row.col.f32.f16.f16.f32 "
                 "{%0,%1,%2,%3}, {%4,%5,%6,%7}, {%8,%9}, {%0,%1,%2,%3};"
                 : "+f"(c[0]), "+f"(c[1]), "+f"(c[2]), "+f"(c[3])
                 : "r"(a0), "r"(a1), "r"(a2), "r"(a3), "r"(b0), "r"(b1));
}

// ===========================================================================
// SMEM layout. Tiles: 128 rows x 256 fp16, row stride 528 B (16B-aligned pad,
// conflict-free for cp.async stores and all ldmatrix 8-address phases).
// ===========================================================================
#define ROWB     528                       // bytes per tile row
#define TILE_B   (128 * ROWB)              // 67584 B
#define SM_A     0
#define SM_B0    TILE_B
#define SM_B1    (2 * TILE_B)
#define SMEM_DYN (3 * TILE_B)              // 202752 B

// order-preserving float->u32 map (ascending)
__device__ __forceinline__ uint32_t fmap(float f) {
    uint32_t b = __float_as_uint(f);
    return b ^ ((b & 0x80000000u) ? 0xFFFFFFFFu : 0x80000000u);
}

// ===========================================================================
// Row L2-normalize (fp32 exact + fp16 copy). One warp per row.
// ===========================================================================
__device__ __forceinline__ void normalize_row(const float* __restrict__ src,
                                              float* __restrict__ dst,
                                              __half* __restrict__ hdst,
                                              int row) {
    int lane = threadIdx.x & 31;
    const float* r = src + (size_t)row * D_;
    float4 a = *reinterpret_cast<const float4*>(r + lane * 8);
    float4 b = *reinterpret_cast<const float4*>(r + lane * 8 + 4);
    float s = a.x*a.x + a.y*a.y + a.z*a.z + a.w*a.w
            + b.x*b.x + b.y*b.y + b.z*b.z + b.w*b.w;
    #pragma unroll
    for (int o = 16; o; o >>= 1) s += __shfl_xor_sync(0xffffffffu, s, o);
    float n = fmaxf(__fsqrt_rn(s), 1e-12f);
    float4 wa, wb;
    wa.x = __fdiv_rn(a.x, n); wa.y = __fdiv_rn(a.y, n);
    wa.z = __fdiv_rn(a.z, n); wa.w = __fdiv_rn(a.w, n);
    wb.x = __fdiv_rn(b.x, n); wb.y = __fdiv_rn(b.y, n);
    wb.z = __fdiv_rn(b.z, n); wb.w = __fdiv_rn(b.w, n);
    float* w = dst + (size_t)row * D_;
    *reinterpret_cast<float4*>(w + lane * 8)     = wa;
    *reinterpret_cast<float4*>(w + lane * 8 + 4) = wb;
    __half2* h = reinterpret_cast<__half2*>(hdst + (size_t)row * D_ + lane * 8);
    h[0] = __floats2half2_rn(wa.x, wa.y);
    h[1] = __floats2half2_rn(wa.z, wa.w);
    h[2] = __floats2half2_rn(wb.x, wb.y);
    h[3] = __floats2half2_rn(wb.z, wb.w);
}

__global__ void k_norm_x(const float* __restrict__ x) {
    int row = blockIdx.x * 8 + (threadIdx.x >> 5);
    normalize_row(x, g_xn, g_xh, row);
}
__global__ void k_norm_cb(const float* __restrict__ emb) {
    int row = blockIdx.x * 8 + (threadIdx.x >> 5);
    normalize_row(emb, g_cbn, g_cbh, row);
}

// ===========================================================================
// Pass 1: raw mma.m16n8k16 fp16 GEMM (dot = zfn . cbn) with register-level
// streaming top-3 per (thread,row). Warp grid 4(m) x 2(n); warp tile 32x64.
// Fragment mapping (PTX ISA): c[e] -> row = g + (e>>1)*8, col = 2*tig + (e&1),
// g = lane>>2, tig = lane&3. Thread folds 64 scores/chunk straight from
// accumulators; per-row candidates = 8 threads x top-3 = 24, merged at end.
// ===========================================================================
__global__ void __launch_bounds__(256, 1) k_argmin_tc() {
    extern __shared__ char smem[];
    const uint32_t sb = smem_to_u32(smem);
    const int tid  = threadIdx.x;
    const int wid  = tid >> 5;
    const int lane = tid & 31;
    const int wm   = wid & 3;          // warp row block (32 rows)
    const int wn   = wid >> 2;         // warp col block (64 cols)
    const int row0 = blockIdx.x * 128;

    // Load A tile (128 rows x 512 B) + first B chunk
    {
        const char* Ag = reinterpret_cast<const char*>(g_xh) + (size_t)row0 * 512;
        const char* Bg = reinterpret_cast<const char*>(g_cbh);
        #pragma unroll
        for (int i = 0; i < 16; i++) {
            int f = tid + i * 256;
            int r = f >> 5, c = f & 31;
            cp16(sb + SM_A + r * ROWB + c * 16, Ag + (size_t)r * 512 + c * 16);
        }
        #pragma unroll
        for (int i = 0; i < 16; i++) {
            int f = tid + i * 256;
            int r = f >> 5, c = f & 31;
            cp16(sb + SM_B0 + r * ROWB + c * 16, Bg + (size_t)r * 512 + c * 16);
        }
        CP_COMMIT();
        CP_WAIT0();
    }
    __syncthreads();

    // ldmatrix per-lane base addresses
    // A (x4, non-trans): lanes 0-15 -> rows 0-15 of the m16 tile, lanes 16-31 -> k+8
    const uint32_t aAddr = sb + SM_A
        + (uint32_t)(wm * 32 + (lane & 15)) * ROWB + (uint32_t)(lane >> 4) * 16;
    // B (x4, non-trans): [tile nt k0-7 | tile nt k8-15 | tile nt+1 k0-7 | tile nt+1 k8-15]
    const uint32_t bOff =
        (uint32_t)(wn * 64 + (lane & 7) + (lane >> 4) * 8) * ROWB
        + (uint32_t)((lane >> 3) & 1) * 16;

    // per-(thread,row) top-3: t = mi*2 + rowhalf
    float tv[4][3];
    int   ti[4][3];
    #pragma unroll
    for (int t = 0; t < 4; t++)
        #pragma unroll
        for (int k = 0; k < 3; k++) { tv[t][k] = -CUDART_INF_F; ti[t][k] = 0; }

    for (int ch = 0; ch < 64; ch++) {
        const uint32_t cur = (ch & 1) ? SM_B1 : SM_B0;
        const uint32_t nxt = (ch & 1) ? SM_B0 : SM_B1;

        // Prefetch next B chunk (overlaps MMA)
        if (ch + 1 < 64) {
            const char* Bg = reinterpret_cast<const char*>(g_cbh)
                           + (size_t)(ch + 1) * 128 * 512;
            #pragma unroll
            for (int i = 0; i < 16; i++) {
                int f = tid + i * 256;
                int r = f >> 5, c = f & 31;
                cp16(sb + nxt + r * ROWB + c * 16, Bg + (size_t)r * 512 + c * 16);
            }
            CP_COMMIT();
        }

        float c[2][8][4];
        #pragma unroll
        for (int mi = 0; mi < 2; mi++)
            #pragma unroll
            for (int nt = 0; nt < 8; nt++)
                #pragma unroll
                for (int e = 0; e < 4; e++) c[mi][nt][e] = 0.0f;

        const uint32_t bAddr = sb + cur + bOff;
        #pragma unroll 4
        for (int ks = 0; ks < 16; ks++) {
            const uint32_t k2 = (uint32_t)ks * 32;  // k0 * 2 bytes
            uint32_t a[2][4];
            ldsm_x4(a[0][0], a[0][1], a[0][2], a[0][3], aAddr + k2);
            ldsm_x4(a[1][0], a[1][1], a[1][2], a[1][3], aAddr + 16 * ROWB + k2);
            #pragma unroll
            for (int ntp = 0; ntp < 4; ntp++) {
                uint32_t b0, b1, b2, b3;
                ldsm_x4(b0, b1, b2, b3, bAddr + (uint32_t)ntp * 16 * ROWB + k2);
                mma16816(c[0][ntp*2],   a[0][0], a[0][1], a[0][2], a[0][3], b0, b1);
                mma16816(c[0][ntp*2+1], a[0][0], a[0][1], a[0][2], a[0][3], b2, b3);
                mma16816(c[1][ntp*2],   a[1][0], a[1][1], a[1][2], a[1][3], b0, b1);
                mma16816(c[1][ntp*2+1], a[1][0], a[1][1], a[1][2], a[1][3], b2, b3);
            }
        }

        // Register epilogue: fold 64 scores into the running top-3 lists
        const int colbase = ch * 128 + wn * 64 + (lane & 3) * 2;
        #pragma unroll
        for (int mi = 0; mi < 2; mi++)
            #pragma unroll
            for (int nt = 0; nt < 8; nt++)
                #pragma unroll
                for (int e = 0; e < 4; e++) {
                    float v = c[mi][nt][e];
                    const int t = mi * 2 + (e >> 1);
                    int col = colbase + nt * 8 + (e & 1);
                    if (v > tv[t][2]) {
                        if (v > tv[t][0]) {
                            tv[t][2]=tv[t][1]; ti[t][2]=ti[t][1];
                            tv[t][1]=tv[t][0]; ti[t][1]=ti[t][0];
                            tv[t][0]=v;        ti[t][0]=col;
                        } else if (v > tv[t][1]) {
                            tv[t][2]=tv[t][1]; ti[t][2]=ti[t][1];
                            tv[t][1]=v;        ti[t][1]=col;
                        } else {
                            tv[t][2]=v;        ti[t][2]=col;
                        }
                    }
                }

        CP_WAIT0();        // next B landed (no-op on last chunk)
        __syncthreads();   // everyone done reading cur; nxt fully valid
    }

    // Merge: 8 threads x top-3 = 24 candidates per row -> top-8
    unsigned long long* ms = reinterpret_cast<unsigned long long*>(smem);
    const int slot = wn * 4 + (lane & 3);          // 0..7
    #pragma unroll
    for (int mi = 0; mi < 2; mi++)
        #pragma unroll
        for (int h = 0; h < 2; h++) {
            int rl = wm * 32 + mi * 16 + h * 8 + (lane >> 2);
            #pragma unroll
            for (int k = 0; k < 3; k++)
                ms[rl * 24 + slot * 3 + k] =
                    ((unsigned long long)fmap(tv[mi*2+h][k]) << 32) |
                    (unsigned)ti[mi*2+h][k];
        }
    __syncthreads();
    if (tid < 128) {
        unsigned long long b8[8];
        #pragma unroll
        for (int k = 0; k < 8; k++) b8[k] = 0ULL;
        #pragma unroll 4
        for (int i = 0; i < 24; i++) {
            unsigned long long key = ms[tid * 24 + i];
            if (key > b8[7]) {
                #pragma unroll
                for (int k = 0; k < 8; k++) {
                    if (key > b8[k]) {
                        unsigned long long tmp = b8[k];
                        b8[k] = key; key = tmp;
                    }
                }
            }
        }
        #pragma unroll
        for (int k = 0; k < 8; k++)
            g_top[(size_t)(row0 + tid) * 8 + k] = (int)(b8[k] & 0xFFFFFFFFu);
    }
}

// ===========================================================================
// Pass 2: re-rank the 8 candidates. Parallel lane layout: cand = lane&7,
// seg = lane>>3 (4 segments x 64 dims). fp32 pass first; rows whose top-2
// gap < 2e-4 (noise is <2e-6) redo in fp64 with the same layout.
// score = |cbn_j|^2 - 2 * (zfn . cbn_j)
// ===========================================================================
__global__ void k_rerank() {
    const int warp = threadIdx.x >> 5, lane = threadIdx.x & 31;
    const int row = blockIdx.x * 8 + warp;
    const int cand = lane & 7;
    const int seg  = lane >> 3;          // 0..3

    const int j = g_top[(size_t)row * 8 + cand];
    const float4* x4 = reinterpret_cast<const float4*>(g_xn  + (size_t)row * D_) + seg * 16;
    const float4* q4 = reinterpret_cast<const float4*>(g_cbn + (size_t)j   * D_) + seg * 16;

    float d = 0.0f, n = 0.0f;
    #pragma unroll
    for (int u = 0; u < 16; u++) {
        float4 qa = q4[u], xa = x4[u];
        d = fmaf(xa.x, qa.x, d); d = fmaf(xa.y, qa.y, d);
        d = fmaf(xa.z, qa.z, d); d = fmaf(xa.w, qa.w, d);
        n = fmaf(qa.x, qa.x, n); n = fmaf(qa.y, qa.y, n);
        n = fmaf(qa.z, qa.z, n); n = fmaf(qa.w, qa.w, n);
    }
    #pragma unroll
    for (int o = 8; o <= 16; o <<= 1) {
        d += __shfl_xor_sync(0xffffffffu, d, o);
        n += __shfl_xor_sync(0xffffffffu, n, o);
    }
    float s = n - 2.0f * d;

    float v1 = s, v2 = CUDART_INF_F;
    int   i1 = j, i2 = 0x7fffffff;
    #pragma unroll
    for (int o = 1; o <= 4; o <<= 1) {
        float ov1 = __shfl_xor_sync(0xffffffffu, v1, o);
        int   oi1 = __shfl_xor_sync(0xffffffffu, i1, o);
        float ov2 = __shfl_xor_sync(0xffffffffu, v2, o);
        int   oi2 = __shfl_xor_sync(0xffffffffu, i2, o);
        if (ov1 < v1 || (ov1 == v1 && oi1 < i1)) {
            v2 = v1; i2 = i1; v1 = ov1; i1 = oi1;
            if (ov2 < v2 || (ov2 == v2 && oi2 < i2)) { v2 = ov2; i2 = oi2; }
        } else {
            if (ov1 < v2 || (ov1 == v2 && oi1 < i2)) { v2 = ov1; i2 = oi1; }
        }
    }

    if (v2 - v1 >= 2e-4f) {
        if (lane == 0) g_bidx[row] = i1;
        return;
    }

    // Rare near-tie: exact fp64 redo, same layout
    double dd = 0.0, nn = 0.0;
    const float* xf = g_xn  + (size_t)row * D_ + seg * 64;
    const float* qf = g_cbn + (size_t)j   * D_ + seg * 64;
    #pragma unroll
    for (int u = 0; u < 64; u++) {
        double qv = (double)qf[u];
        dd += (double)xf[u] * qv;
        nn += qv * qv;
    }
    #pragma unroll
    for (int o = 8; o <= 16; o <<= 1) {
        dd += __shfl_xor_sync(0xffffffffu, dd, o);
        nn += __shfl_xor_sync(0xffffffffu, nn, o);
    }
    double sd = nn - 2.0 * dd;
    double bv = sd; int bidx = j;
    #pragma unroll
    for (int o = 1; o <= 4; o <<= 1) {
        double ov = __shfl_xor_sync(0xffffffffu, bv, o);
        int    oi = __shfl_xor_sync(0xffffffffu, bidx, o);
        if (ov < bv || (ov == bv && oi < bidx)) { bv = ov; bidx = oi; }
    }
    if (lane == 0) g_bidx[row] = bidx;
}

// ===========================================================================
// Quantize + partial loss: one warp per row.
// z_out = x + (zqn - x)  (reference rounding order), zqn = g_cbn[idx].
// ===========================================================================
__global__ void k_quant(const float* __restrict__ x, float* __restrict__ out) {
    int warp = threadIdx.x >> 5, lane = threadIdx.x & 31;
    int row = blockIdx.x * 8 + warp;
    int j = g_bidx[row];
    const float* q  = g_cbn + (size_t)j   * D_;
    const float* xr = x     + (size_t)row * D_;
    const float* zn = g_xn  + (size_t)row * D_;
    float acc = 0.0f;
    #pragma unroll
    for (int u = 0; u < 8; u++) {
        int c = lane * 8 + u;
        float qv = q[c];
        float xv = xr[c];
        out[(size_t)row * D_ + c] = xv + (qv - xv);
        float dd = qv - zn[c];
        acc = fmaf(dd, dd, acc);
    }
    #pragma unroll
    for (int o = 16; o; o >>= 1) acc += __shfl_xor_sync(0xffffffffu, acc, o);
    __shared__ float ws[8];
    if (lane == 0) ws[warp] = acc;
    __syncthreads();
    if (threadIdx.x == 0) {
        float s = 0.0f;
        #pragma unroll
        for (int w = 0; w < 8; w++) s += ws[w];
        g_part[blockIdx.x] = s;
    }
    if (lane == 0) out[ZOUT_ELEMS + 1 + row] = (float)j;
}

// Deterministic final loss reduction (double accumulation for the big sum)
__global__ void k_loss(float* __restrict__ out) {
    __shared__ double sm[256];
    double s = 0.0;
    for (int i = threadIdx.x; i < BT_ / 8; i += 256) s += (double)g_part[i];
    sm[threadIdx.x] = s;
    __syncthreads();
    for (int o = 128; o; o >>= 1) {
        if (threadIdx.x < o) sm[threadIdx.x] += sm[threadIdx.x + o];
        __syncthreads();
    }
    if (threadIdx.x == 0) {
        float m = (float)(sm[0] / (double)(BT_ * D_));
        out[ZOUT_ELEMS] = 0.25f * m + m;   // BETA*mean + mean
    }
}

// ===========================================================================
extern "C" void kernel_launch(void* const* d_in, const int* in_sizes, int n_in,
                              void* d_out, int out_size) {
    const float* x   = (const float*)d_in[0];  // [32,1024,256]
    const float* emb = (const float*)d_in[1];  // [8192,256]
    float* out = (float*)d_out;

    cudaFuncSetAttribute(k_argmin_tc,
                         cudaFuncAttributeMaxDynamicSharedMemorySize, SMEM_DYN);

    k_norm_cb<<<NC_ / 8, 256>>>(emb);            // normalized codebook + fp16
    k_norm_x <<<BT_ / 8, 256>>>(x);              // normalized inputs + fp16
    k_argmin_tc<<<BT_ / 128, 256, SMEM_DYN>>>(); // raw-MMA GEMM + reg top-3
    k_rerank <<<BT_ / 8, 256>>>();               // parallel re-rank + fp64 rescue
    k_quant  <<<BT_ / 8, 256>>>(x, out);         // z_out, idx, loss partials
    k_loss   <<<1, 256>>>(out);                  // deterministic loss reduce
}